// round 16
// baseline (speedup 1.0000x reference)
#include <cuda_runtime.h>
#include <math.h>

#define NN 2048
#define NE 4096
#define DD 128
#define NHEAD 4
#define DHEAD 32
#define NK 819     /* int(0.4*2048) */
#define EK 1638    /* int(0.4*4096) */
#define CAP 64     /* per-node incidence capacity (max random degree ~20) */
#define MAXC 128
#define NB 128     /* persistent prep grid: <= SM count, residency-safe */
#define NBAR 2

// ---------------- scratch (device globals; no allocation allowed) ----------------
__device__ unsigned g_bar[NBAR];     // global barrier counters (self-resetting)
__device__ float g_nscore[NN];
__device__ float g_escore[NE];
__device__ unsigned g_nthr, g_ethr;  // top-k thresholds (order-mapped uint space)
__device__ int   g_emask[NE];
__device__ int   g_cnt[NN];
__device__ int   g_adj[NN * CAP];
__device__ int   g_epk[NE];          // (src<<16)|dst
__device__ float g_nk2[NN * DD];     // nf @ Wk[128:256]
__device__ float g_nk3[NN * DD];     // nf @ Wk[256:384]
__device__ float g_nv2[NN * DD];     // nf @ Wv[128:256]
__device__ float g_nv3[NN * DD];     // nf @ Wv[256:384]
__device__ float g_q[NE * DD];
__device__ float g_k[NE * DD];
__device__ float g_v[NE * DD];
__device__ float g_ctx[NE * DD];
__device__ float g_wf[DD * DD];      // Wo @ W1   (computed in k_kvq extra blocks)
__device__ float g_bf[DD];           // bo @ W1 + b1
__device__ float g_c1[NE * DD];      // wef @ W1 (masked edges only)

// Device-wide barrier (validated R9-R15: correctness + graph replay).
__device__ __forceinline__ void gbar(int p) {
    __syncthreads();
    if (threadIdx.x == 0) {
        __threadfence();
        atomicAdd(&g_bar[p], 1u);
        while (((volatile unsigned*)g_bar)[p] < NB) { }
        __threadfence();
        if (blockIdx.x == 0) g_bar[(p + NBAR - 1) % NBAR] = 0;
    }
    __syncthreads();
}

// order-preserving float -> uint map (x > y  <=>  map(x) > map(y))
__device__ __forceinline__ unsigned fmap(float x) {
    unsigned u = __float_as_uint(x);
    return (u & 0x80000000u) ? ~u : (u | 0x80000000u);
}

__device__ __forceinline__ float wsum(float v) {
    v += __shfl_xor_sync(0xffffffffu, v, 16);
    v += __shfl_xor_sync(0xffffffffu, v, 8);
    v += __shfl_xor_sync(0xffffffffu, v, 4);
    v += __shfl_xor_sync(0xffffffffu, v, 2);
    v += __shfl_xor_sync(0xffffffffu, v, 1);
    return v;
}
__device__ __forceinline__ float wmax(float v) {
    v = fmaxf(v, __shfl_xor_sync(0xffffffffu, v, 16));
    v = fmaxf(v, __shfl_xor_sync(0xffffffffu, v, 8));
    v = fmaxf(v, __shfl_xor_sync(0xffffffffu, v, 4));
    v = fmaxf(v, __shfl_xor_sync(0xffffffffu, v, 2));
    v = fmaxf(v, __shfl_xor_sync(0xffffffffu, v, 1));
    return v;
}
__device__ __forceinline__ int wsumi(int v) {
    v += __shfl_xor_sync(0xffffffffu, v, 16);
    v += __shfl_xor_sync(0xffffffffu, v, 8);
    v += __shfl_xor_sync(0xffffffffu, v, 4);
    v += __shfl_xor_sync(0xffffffffu, v, 2);
    v += __shfl_xor_sync(0xffffffffu, v, 1);
    return v;
}

// ============ 1) persistent prep: nodeproj+scores | thresholds | build ============
__global__ __launch_bounds__(256) void k_prep(
    const float* __restrict__ nf, const float* __restrict__ ef, const int* __restrict__ ei,
    const float* __restrict__ wn, const float* __restrict__ we,
    const float* __restrict__ Wk, const float* __restrict__ Wv)
{
    __shared__ __align__(16) float Ast[2][16][68];
    __shared__ __align__(16) float Bs[2][16][128];
    __shared__ unsigned sbuf[NE];        // 16KB: mapped scores for threshold select
    __shared__ int scnt;
    int tid = threadIdx.x;
    int bid = blockIdx.x;
    int wid = tid >> 5, lane = tid & 31;

    // ---- Phase A: zero counters + nodeproj tile + scores ----
    {
        int gid = bid * 256 + tid;
        if (gid < NN) g_cnt[gid] = 0;

        int y = bid >> 5;
        int rb = (bid & 31) * 64;
        const float* B = (y == 0) ? Wk + 128 * DD : (y == 1) ? Wk + 256 * DD
                       : (y == 2) ? Wv + 128 * DD : Wv + 256 * DD;
        float* C = (y == 0) ? g_nk2 : (y == 1) ? g_nk3 : (y == 2) ? g_nv2 : g_nv3;

        int ty = tid >> 4, tx = tid & 15;
        float acc[4][8];
#pragma unroll
        for (int i = 0; i < 4; i++)
#pragma unroll
            for (int j = 0; j < 8; j++) acc[i][j] = 0.f;

        float aReg[4];
        float4 bReg[2];
        auto loadT = [&](int t) {
            int k0 = t * 16;
#pragma unroll
            for (int l = 0; l < 4; l++) {
                int idx = tid + l * 256;
                int kk = idx & 15, r = idx >> 4;
                aReg[l] = nf[(size_t)(rb + r) * DD + k0 + kk];
            }
            const float4* src = (const float4*)(B + (size_t)k0 * DD);
            bReg[0] = src[tid];
            bReg[1] = src[tid + 256];
        };
        auto storeT = [&](int buf) {
#pragma unroll
            for (int l = 0; l < 4; l++) {
                int idx = tid + l * 256;
                Ast[buf][idx & 15][idx >> 4] = aReg[l];
            }
            float4* dst = (float4*)&Bs[buf][0][0];
            dst[tid] = bReg[0];
            dst[tid + 256] = bReg[1];
        };

        loadT(0);
        storeT(0);
        __syncthreads();
        const int T = 8;
        for (int t = 0; t < T; t++) {
            int buf = t & 1;
            if (t + 1 < T) loadT(t + 1);
#pragma unroll
            for (int kk = 0; kk < 16; kk++) {
                float a[4], b[8];
                *(float4*)&a[0] = *(const float4*)&Ast[buf][kk][ty * 4];
                *(float4*)&b[0] = *(const float4*)&Bs[buf][kk][tx * 8];
                *(float4*)&b[4] = *(const float4*)&Bs[buf][kk][tx * 8 + 4];
#pragma unroll
                for (int i = 0; i < 4; i++)
#pragma unroll
                    for (int j = 0; j < 8; j++) acc[i][j] += a[i] * b[j];
            }
            __syncthreads();
            if (t + 1 < T) {
                storeT(buf ^ 1);
                __syncthreads();
            }
        }
#pragma unroll
        for (int i = 0; i < 4; i++) {
            int row = rb + ty * 4 + i;
            float4 o0 = {acc[i][0], acc[i][1], acc[i][2], acc[i][3]};
            float4 o1 = {acc[i][4], acc[i][5], acc[i][6], acc[i][7]};
            *(float4*)&C[(size_t)row * DD + tx * 8] = o0;
            *(float4*)&C[(size_t)row * DD + tx * 8 + 4] = o1;
        }

        // scores: warp per row over N+E rows
        int wg = bid * 8 + wid;
        for (int row = wg; row < NN + NE; row += NB * 8) {
            const float* base;
            const float* w;
            if (row < NN) { base = nf + (size_t)row * DD; w = wn; }
            else          { base = ef + (size_t)(row - NN) * DD; w = we; }
            float s = 0.f;
#pragma unroll
            for (int l = 0; l < 4; l++) {
                int d = lane + l * 32;
                s += base[d] * w[d];
            }
            s = wsum(s);
            if (lane == 0) {
                if (row < NN) g_nscore[row] = s;
                else          g_escore[row - NN] = s;
            }
        }
    }
    gbar(0);

    // ---- Phase B: exact top-k THRESHOLDS via 32-bit radix descent (blocks 0,1) ----
    // t_final = k-th largest mapped value; mask = mapped(score) >= t_final selects
    // exactly the top-k set (distinct values), bit-identical to rank counting.
    if (bid <= 1) {
        int n = (bid == 0) ? NN : NE;
        int k = (bid == 0) ? NK : EK;
        const float* src = (bid == 0) ? g_nscore : g_escore;
        for (int i = tid; i < n; i += 256) sbuf[i] = fmap(src[i]);
        __syncthreads();
        unsigned t = 0;
        for (int bit = 31; bit >= 0; bit--) {
            unsigned cand = t | (1u << bit);
            if (tid == 0) scnt = 0;
            __syncthreads();
            int c = 0;
            for (int i = tid; i < n; i += 256) c += (sbuf[i] >= cand);
            c = wsumi(c);
            if (lane == 0) atomicAdd(&scnt, c);
            __syncthreads();
            unsigned ok = (scnt >= k);
            __syncthreads();             // protect scnt before next zeroing
            if (ok) t = cand;
        }
        if (tid == 0) {
            if (bid == 0) g_nthr = t;
            else          g_ethr = t;
        }
    }
    gbar(1);

    // ---- Phase C: edge mask + incidence lists (bid 0-15 only) ----
    {
        int e = bid * 256 + tid;
        if (e < NE) {
            unsigned nthr = g_nthr, ethr = g_ethr;
            int s = ei[e], d = ei[NE + e];
            g_epk[e] = (s << 16) | d;
            g_emask[e] = (fmap(g_escore[e]) >= ethr &&
                          fmap(g_nscore[s]) >= nthr &&
                          fmap(g_nscore[d]) >= nthr) ? 1 : 0;
            int p = atomicAdd(&g_cnt[s], 1);
            if (p < CAP) g_adj[s * CAP + p] = e;
            if (d != s) {
                p = atomicAdd(&g_cnt[d], 1);
                if (p < CAP) g_adj[d * CAP + p] = e;
            }
        }
    }
}

// ============ 2) Q/K/V assembly + sparse corrections + Wf/bf (extra blocks) ============
__global__ __launch_bounds__(128) void k_kvq(
    const float* __restrict__ ef,
    const float* __restrict__ Wq, const float* __restrict__ Wk, const float* __restrict__ Wv,
    const float* __restrict__ W1,
    const float* __restrict__ bq, const float* __restrict__ bk, const float* __restrict__ bv,
    const float* __restrict__ Wo, const float* __restrict__ bo, const float* __restrict__ b1)
{
    __shared__ float efs[DD];
    int e = blockIdx.x;
    int c = threadIdx.x;

    if (e >= NE) {
        int wb = e - NE;
        if (wb < DD) {
            efs[c] = Wo[(size_t)wb * DD + c];
            __syncthreads();
            float a0 = 0.f, a1 = 0.f, a2 = 0.f, a3 = 0.f;
#pragma unroll 4
            for (int k = 0; k < DD; k += 4) {
                a0 += efs[k + 0] * W1[(k + 0) * DD + c];
                a1 += efs[k + 1] * W1[(k + 1) * DD + c];
                a2 += efs[k + 2] * W1[(k + 2) * DD + c];
                a3 += efs[k + 3] * W1[(k + 3) * DD + c];
            }
            g_wf[(size_t)wb * DD + c] = (a0 + a1) + (a2 + a3);
        } else {
            efs[c] = bo[c];
            __syncthreads();
            float a = 0.f;
#pragma unroll 4
            for (int k = 0; k < DD; k++) a += efs[k] * W1[k * DD + c];
            g_bf[c] = a + b1[c];
        }
        return;
    }

    int pk = g_epk[e];
    int s = pk >> 16, d = pk & 0xffff;

    float kacc = g_nk2[(size_t)s * DD + c] + g_nk3[(size_t)d * DD + c] + bk[c];
    float vacc = g_nv2[(size_t)s * DD + c] + g_nv3[(size_t)d * DD + c] + bv[c];
    float qacc = bq[c];

    if (g_emask[e]) {                       // block-uniform branch
        efs[c] = ef[(size_t)e * DD + c];
        __syncthreads();
        float c1 = 0.f;
#pragma unroll 4
        for (int k = 0; k < DD; k++) {
            float a = efs[k];
            qacc += a * Wq[k * DD + c];
            kacc += a * Wk[k * DD + c];
            vacc += a * Wv[k * DD + c];
            c1   += a * W1[k * DD + c];
        }
        g_c1[(size_t)e * DD + c] = c1;
    }
    g_q[(size_t)e * DD + c] = qacc;
    g_k[(size_t)e * DD + c] = kacc;
    g_v[(size_t)e * DD + c] = vacc;
}

// ============ 3) sparse edge attention (block/edge, warp/head) ============
__global__ __launch_bounds__(128) void k_attn() {
    __shared__ int cand[MAXC];
    __shared__ int s_nc;
    __shared__ float sc[NHEAD][MAXC];
    int e = blockIdx.x;
    int tid = threadIdx.x;
    int pk = g_epk[e];
    int qs = pk >> 16, qd = pk & 0xffff;
    if (tid == 0) {
        int n = 0;
        int cs = min(g_cnt[qs], CAP);
        for (int p = 0; p < cs; p++) cand[n++] = g_adj[qs * CAP + p];
        if (qd != qs) {
            int cd = min(g_cnt[qd], CAP);
            for (int p = 0; p < cd; p++) {
                int f = g_adj[qd * CAP + p];
                int fp = g_epk[f];
                if ((fp >> 16) != qs && (fp & 0xffff) != qs) cand[n++] = f;
            }
        }
        s_nc = n;
    }
    __syncthreads();
    int nc = s_nc;
    int h = tid >> 5, lane = tid & 31;
    float qv = g_q[(size_t)e * DD + h * DHEAD + lane];
    const float scale = 0.17677669529663687f; // 1/sqrt(32)
    for (int c = 0; c < nc; c++) {
        int f = cand[c];
        float t = qv * g_k[(size_t)f * DD + h * DHEAD + lane];
        t = wsum(t);
        if (lane == 0) sc[h][c] = t * scale;
    }
    __syncwarp();
    float m = -1e30f;
    for (int c = lane; c < nc; c += 32) m = fmaxf(m, sc[h][c]);
    m = wmax(m);
    float l = 0.f;
    for (int c = lane; c < nc; c += 32) {
        float p = expf(sc[h][c] - m);
        sc[h][c] = p;
        l += p;
    }
    l = wsum(l);
    __syncwarp();
    float acc = 0.f;
    for (int c = 0; c < nc; c++)
        acc += sc[h][c] * g_v[(size_t)cand[c] * DD + h * DHEAD + lane];
    g_ctx[(size_t)e * DD + h * DHEAD + lane] = acc / l;
}

// ============ 4) tail: 32-row tile, 128 thr, 4x8 microtile, K-chunk 32 (R15) ========
// hid = gelu(ctx@Wf + bf + mask*c1); out = hid@W2 + b2. 8 syncs total.
__global__ __launch_bounds__(128) void k_tail(
    const float* __restrict__ W2, const float* __restrict__ b2,
    float* __restrict__ out)
{
    __shared__ __align__(16) float Ast[2][32][36];  // ctx^T [buf][kk(32)][row(32)]
    __shared__ __align__(16) float Bs[2][32][128];  // Wf    [buf][kk(32)][col]
    __shared__ float sm_m[32];

    int tid = threadIdx.x;
    int rb = blockIdx.x * 32;
    if (tid < 32) sm_m[tid] = g_emask[rb + tid] ? 1.f : 0.f;

    int ty = tid >> 4, tx = tid & 15;   // ty 0..7 (4 rows), tx 0..15 (8 cols)
    float acc[4][8];
#pragma unroll
    for (int i = 0; i < 4; i++)
#pragma unroll
        for (int j = 0; j < 8; j++) acc[i][j] = 0.f;

    float aReg[8];
    float4 bReg[8];
    auto loadT = [&](int t) {
        int k0 = t * 32;
#pragma unroll
        for (int l = 0; l < 8; l++) {
            int idx = tid + l * 128;        // 0..1023 over [kk(32) x row(32)]
            int kk = idx & 31, r = idx >> 5;
            aReg[l] = g_ctx[(size_t)(rb + r) * DD + k0 + kk];
        }
        const float4* src = (const float4*)(g_wf + (size_t)k0 * DD);
#pragma unroll
        for (int l = 0; l < 8; l++) bReg[l] = src[tid + l * 128];
    };
    auto storeT = [&](int buf) {
#pragma unroll
        for (int l = 0; l < 8; l++) {
            int idx = tid + l * 128;
            Ast[buf][idx & 31][idx >> 5] = aReg[l];
        }
        float4* dst = (float4*)&Bs[buf][0][0];
#pragma unroll
        for (int l = 0; l < 8; l++) dst[tid + l * 128] = bReg[l];
    };

    loadT(0);
    storeT(0);
    __syncthreads();
    const int T = 4;
    for (int t = 0; t < T; t++) {
        int buf = t & 1;
        if (t + 1 < T) loadT(t + 1);
#pragma unroll
        for (int kk = 0; kk < 32; kk++) {
            float a[4], b[8];
            *(float4*)&a[0] = *(const float4*)&Ast[buf][kk][ty * 4];
            *(float4*)&b[0] = *(const float4*)&Bs[buf][kk][tx * 8];
            *(float4*)&b[4] = *(const float4*)&Bs[buf][kk][tx * 8 + 4];
#pragma unroll
            for (int i = 0; i < 4; i++)
#pragma unroll
                for (int j = 0; j < 8; j++) acc[i][j] += a[i] * b[j];
        }
        __syncthreads();
        if (t + 1 < T) {
            storeT(buf ^ 1);
            __syncthreads();
        }
    }

    // epilogue: + bf + masked c1, gelu (tanh approx = jax.nn.gelu default)
#pragma unroll
    for (int i = 0; i < 4; i++) {
        int r = ty * 4 + i;
        int row = rb + r;
        bool msk = (sm_m[r] != 0.f);
#pragma unroll
        for (int j = 0; j < 8; j++) {
            int col = tx * 8 + j;
            float x = acc[i][j] + g_bf[col];
            if (msk) x += g_c1[(size_t)row * DD + col];
            acc[i][j] = 0.5f * x * (1.f + tanhf(0.7978845608028654f * (x + 0.044715f * x * x * x)));
        }
    }

    // out = hid @ W2 + b2 (register partials + shfl reduce over tx)
    float4 w4[8];
#pragma unroll
    for (int j = 0; j < 8; j++) w4[j] = *(const float4*)&W2[(tx * 8 + j) * 4];

#pragma unroll
    for (int i = 0; i < 4; i++) {
        float p0 = 0.f, p1 = 0.f, p2 = 0.f, p3 = 0.f;
#pragma unroll
        for (int j = 0; j < 8; j++) {
            float h = acc[i][j];
            p0 += h * w4[j].x;
            p1 += h * w4[j].y;
            p2 += h * w4[j].z;
            p3 += h * w4[j].w;
        }
#pragma unroll
        for (int off = 1; off < 16; off <<= 1) {
            p0 += __shfl_xor_sync(0xffffffffu, p0, off);
            p1 += __shfl_xor_sync(0xffffffffu, p1, off);
            p2 += __shfl_xor_sync(0xffffffffu, p2, off);
            p3 += __shfl_xor_sync(0xffffffffu, p3, off);
        }
        if (tx == 0) {
            int row = rb + ty * 4 + i;
            out[row * 4 + 0] = p0 + b2[0];
            out[row * 4 + 1] = p1 + b2[1];
            out[row * 4 + 2] = p2 + b2[2];
            out[row * 4 + 3] = p3 + b2[3];
        }
    }
}

// ---------------- launch ----------------
extern "C" void kernel_launch(void* const* d_in, const int* in_sizes, int n_in,
                              void* d_out, int out_size) {
    const float* nf = (const float*)d_in[0];
    const float* ef = (const float*)d_in[1];
    const int*   ei = (const int*)d_in[2];
    const float* wn = (const float*)d_in[3];
    const float* we = (const float*)d_in[4];
    const float* Wq = (const float*)d_in[5];
    const float* bq = (const float*)d_in[6];
    const float* Wk = (const float*)d_in[7];
    const float* bk = (const float*)d_in[8];
    const float* Wv = (const float*)d_in[9];
    const float* bv = (const float*)d_in[10];
    const float* Wo = (const float*)d_in[11];
    const float* bo = (const float*)d_in[12];
    const float* W1 = (const float*)d_in[13];
    const float* b1 = (const float*)d_in[14];
    const float* W2 = (const float*)d_in[15];
    const float* b2 = (const float*)d_in[16];
    float* out = (float*)d_out;

    k_prep<<<NB, 256>>>(nf, ef, ei, wn, we, Wk, Wv);
    k_kvq<<<NE + DD + 1, 128>>>(ef, Wq, Wk, Wv, W1, bq, bk, bv, Wo, bo, b1);
    k_attn<<<4096, 128>>>();
    k_tail<<<128, 128>>>(W2, b2, out);
}

// round 17
// speedup vs baseline: 1.0892x; 1.0892x over previous
#include <cuda_runtime.h>
#include <math.h>

#define NN 2048
#define NE 4096
#define DD 128
#define NHEAD 4
#define DHEAD 32
#define NK 819     /* int(0.4*2048) */
#define EK 1638    /* int(0.4*4096) */
#define CAP 64     /* per-node incidence capacity (max random degree ~20) */
#define MAXC 128
#define NB 128     /* persistent prep grid: <= SM count, residency-safe */
#define NBAR 2

// ---------------- scratch (device globals; no allocation allowed) ----------------
__device__ unsigned g_bar[NBAR];     // global barrier counters (self-resetting)
__device__ float g_nscore[NN];
__device__ float g_escore[NE];
__device__ int   g_nmask[NN];
__device__ int   g_etop[NE];
__device__ int   g_emask[NE];
__device__ int   g_cnt[NN];
__device__ int   g_adj[NN * CAP];
__device__ int   g_epk[NE];          // (src<<16)|dst
__device__ float g_nk2[NN * DD];     // nf @ Wk[128:256]
__device__ float g_nk3[NN * DD];     // nf @ Wk[256:384]
__device__ float g_nv2[NN * DD];     // nf @ Wv[128:256]
__device__ float g_nv3[NN * DD];     // nf @ Wv[256:384]
__device__ float g_q[NE * DD];
__device__ float g_k[NE * DD];
__device__ float g_v[NE * DD];
__device__ float g_ctx[NE * DD];
__device__ float g_wf[DD * DD];      // Wo @ W1   (computed in k_kvq extra blocks)
__device__ float g_bf[DD];           // bo @ W1 + b1
__device__ float g_c1[NE * DD];      // wef @ W1 (masked edges only)

// Device-wide barrier (validated R9-R16: correctness + graph replay).
__device__ __forceinline__ void gbar(int p) {
    __syncthreads();
    if (threadIdx.x == 0) {
        __threadfence();
        atomicAdd(&g_bar[p], 1u);
        while (((volatile unsigned*)g_bar)[p] < NB) { }
        __threadfence();
        if (blockIdx.x == 0) g_bar[(p + NBAR - 1) % NBAR] = 0;
    }
    __syncthreads();
}

__device__ __forceinline__ float wsum(float v) {
    v += __shfl_xor_sync(0xffffffffu, v, 16);
    v += __shfl_xor_sync(0xffffffffu, v, 8);
    v += __shfl_xor_sync(0xffffffffu, v, 4);
    v += __shfl_xor_sync(0xffffffffu, v, 2);
    v += __shfl_xor_sync(0xffffffffu, v, 1);
    return v;
}
__device__ __forceinline__ float wmax(float v) {
    v = fmaxf(v, __shfl_xor_sync(0xffffffffu, v, 16));
    v = fmaxf(v, __shfl_xor_sync(0xffffffffu, v, 8));
    v = fmaxf(v, __shfl_xor_sync(0xffffffffu, v, 4));
    v = fmaxf(v, __shfl_xor_sync(0xffffffffu, v, 2));
    v = fmaxf(v, __shfl_xor_sync(0xffffffffu, v, 1));
    return v;
}
__device__ __forceinline__ int wsumi(int v) {
    v += __shfl_xor_sync(0xffffffffu, v, 16);
    v += __shfl_xor_sync(0xffffffffu, v, 8);
    v += __shfl_xor_sync(0xffffffffu, v, 4);
    v += __shfl_xor_sync(0xffffffffu, v, 2);
    v += __shfl_xor_sync(0xffffffffu, v, 1);
    return v;
}

// ============ 1) persistent prep: nodeproj+scores | masks | build (R15) ============
__global__ __launch_bounds__(256) void k_prep(
    const float* __restrict__ nf, const float* __restrict__ ef, const int* __restrict__ ei,
    const float* __restrict__ wn, const float* __restrict__ we,
    const float* __restrict__ Wk, const float* __restrict__ Wv)
{
    __shared__ __align__(16) float Ast[2][16][68];
    __shared__ __align__(16) float Bs[2][16][128];
    int tid = threadIdx.x;
    int bid = blockIdx.x;
    int wid = tid >> 5, lane = tid & 31;

    // ---- Phase A: zero counters + nodeproj tile + scores ----
    {
        int gid = bid * 256 + tid;
        if (gid < NN) g_cnt[gid] = 0;

        int y = bid >> 5;
        int rb = (bid & 31) * 64;
        const float* B = (y == 0) ? Wk + 128 * DD : (y == 1) ? Wk + 256 * DD
                       : (y == 2) ? Wv + 128 * DD : Wv + 256 * DD;
        float* C = (y == 0) ? g_nk2 : (y == 1) ? g_nk3 : (y == 2) ? g_nv2 : g_nv3;

        int ty = tid >> 4, tx = tid & 15;
        float acc[4][8];
#pragma unroll
        for (int i = 0; i < 4; i++)
#pragma unroll
            for (int j = 0; j < 8; j++) acc[i][j] = 0.f;

        float aReg[4];
        float4 bReg[2];
        auto loadT = [&](int t) {
            int k0 = t * 16;
#pragma unroll
            for (int l = 0; l < 4; l++) {
                int idx = tid + l * 256;
                int kk = idx & 15, r = idx >> 4;
                aReg[l] = nf[(size_t)(rb + r) * DD + k0 + kk];
            }
            const float4* src = (const float4*)(B + (size_t)k0 * DD);
            bReg[0] = src[tid];
            bReg[1] = src[tid + 256];
        };
        auto storeT = [&](int buf) {
#pragma unroll
            for (int l = 0; l < 4; l++) {
                int idx = tid + l * 256;
                Ast[buf][idx & 15][idx >> 4] = aReg[l];
            }
            float4* dst = (float4*)&Bs[buf][0][0];
            dst[tid] = bReg[0];
            dst[tid + 256] = bReg[1];
        };

        loadT(0);
        storeT(0);
        __syncthreads();
        const int T = 8;
        for (int t = 0; t < T; t++) {
            int buf = t & 1;
            if (t + 1 < T) loadT(t + 1);
#pragma unroll
            for (int kk = 0; kk < 16; kk++) {
                float a[4], b[8];
                *(float4*)&a[0] = *(const float4*)&Ast[buf][kk][ty * 4];
                *(float4*)&b[0] = *(const float4*)&Bs[buf][kk][tx * 8];
                *(float4*)&b[4] = *(const float4*)&Bs[buf][kk][tx * 8 + 4];
#pragma unroll
                for (int i = 0; i < 4; i++)
#pragma unroll
                    for (int j = 0; j < 8; j++) acc[i][j] += a[i] * b[j];
            }
            __syncthreads();
            if (t + 1 < T) {
                storeT(buf ^ 1);
                __syncthreads();
            }
        }
#pragma unroll
        for (int i = 0; i < 4; i++) {
            int row = rb + ty * 4 + i;
            float4 o0 = {acc[i][0], acc[i][1], acc[i][2], acc[i][3]};
            float4 o1 = {acc[i][4], acc[i][5], acc[i][6], acc[i][7]};
            *(float4*)&C[(size_t)row * DD + tx * 8] = o0;
            *(float4*)&C[(size_t)row * DD + tx * 8 + 4] = o1;
        }

        // scores: warp per row over N+E rows
        int wg = bid * 8 + wid;
        for (int row = wg; row < NN + NE; row += NB * 8) {
            const float* base;
            const float* w;
            if (row < NN) { base = nf + (size_t)row * DD; w = wn; }
            else          { base = ef + (size_t)(row - NN) * DD; w = we; }
            float s = 0.f;
#pragma unroll
            for (int l = 0; l < 4; l++) {
                int d = lane + l * 32;
                s += base[d] * w[d];
            }
            s = wsum(s);
            if (lane == 0) {
                if (row < NN) g_nscore[row] = s;
                else          g_escore[row - NN] = s;
            }
        }
    }
    gbar(0);

    // ---- Phase B: exact top-k masks via rank counting (float4, L1-resident) ----
    {
        const float4* ns4 = (const float4*)g_nscore;
        const float4* es4 = (const float4*)g_escore;
        int wg = bid * 8 + wid;
        for (int row = wg; row < NN + NE; row += NB * 8) {
            if (row < NN) {
                float s = g_nscore[row];
                int c = 0;
                for (int j = lane; j < NN / 4; j += 32) {
                    float4 f = ns4[j];
                    c += (f.x > s) + (f.y > s) + (f.z > s) + (f.w > s);
                }
                c = wsumi(c);
                if (lane == 0) g_nmask[row] = (c < NK);
            } else {
                int e = row - NN;
                float s = g_escore[e];
                int c = 0;
                for (int j = lane; j < NE / 4; j += 32) {
                    float4 f = es4[j];
                    c += (f.x > s) + (f.y > s) + (f.z > s) + (f.w > s);
                }
                c = wsumi(c);
                if (lane == 0) g_etop[e] = (c < EK);
            }
        }
    }
    gbar(1);

    // ---- Phase C: edge mask + incidence lists (bid 0-15 only) ----
    {
        int e = bid * 256 + tid;
        if (e < NE) {
            int s = ei[e], d = ei[NE + e];
            g_epk[e] = (s << 16) | d;
            g_emask[e] = (g_etop[e] && g_nmask[s] && g_nmask[d]) ? 1 : 0;
            int p = atomicAdd(&g_cnt[s], 1);
            if (p < CAP) g_adj[s * CAP + p] = e;
            if (d != s) {
                p = atomicAdd(&g_cnt[d], 1);
                if (p < CAP) g_adj[d * CAP + p] = e;
            }
        }
    }
}

// ============ 2) Q/K/V assembly + sparse corrections + Wf/bf (extra blocks) ============
__global__ __launch_bounds__(128) void k_kvq(
    const float* __restrict__ ef,
    const float* __restrict__ Wq, const float* __restrict__ Wk, const float* __restrict__ Wv,
    const float* __restrict__ W1,
    const float* __restrict__ bq, const float* __restrict__ bk, const float* __restrict__ bv,
    const float* __restrict__ Wo, const float* __restrict__ bo, const float* __restrict__ b1)
{
    __shared__ float efs[DD];
    int e = blockIdx.x;
    int c = threadIdx.x;

    if (e >= NE) {
        int wb = e - NE;
        if (wb < DD) {
            efs[c] = Wo[(size_t)wb * DD + c];
            __syncthreads();
            float a0 = 0.f, a1 = 0.f, a2 = 0.f, a3 = 0.f;
#pragma unroll 4
            for (int k = 0; k < DD; k += 4) {
                a0 += efs[k + 0] * W1[(k + 0) * DD + c];
                a1 += efs[k + 1] * W1[(k + 1) * DD + c];
                a2 += efs[k + 2] * W1[(k + 2) * DD + c];
                a3 += efs[k + 3] * W1[(k + 3) * DD + c];
            }
            g_wf[(size_t)wb * DD + c] = (a0 + a1) + (a2 + a3);
        } else {
            efs[c] = bo[c];
            __syncthreads();
            float a = 0.f;
#pragma unroll 4
            for (int k = 0; k < DD; k++) a += efs[k] * W1[k * DD + c];
            g_bf[c] = a + b1[c];
        }
        return;
    }

    int pk = g_epk[e];
    int s = pk >> 16, d = pk & 0xffff;

    float kacc = g_nk2[(size_t)s * DD + c] + g_nk3[(size_t)d * DD + c] + bk[c];
    float vacc = g_nv2[(size_t)s * DD + c] + g_nv3[(size_t)d * DD + c] + bv[c];
    float qacc = bq[c];

    if (g_emask[e]) {                       // block-uniform branch
        efs[c] = ef[(size_t)e * DD + c];
        __syncthreads();
        float c1 = 0.f;
#pragma unroll 4
        for (int k = 0; k < DD; k++) {
            float a = efs[k];
            qacc += a * Wq[k * DD + c];
            kacc += a * Wk[k * DD + c];
            vacc += a * Wv[k * DD + c];
            c1   += a * W1[k * DD + c];
        }
        g_c1[(size_t)e * DD + c] = c1;
    }
    g_q[(size_t)e * DD + c] = qacc;
    g_k[(size_t)e * DD + c] = kacc;
    g_v[(size_t)e * DD + c] = vacc;
}

// ============ 3) sparse edge attention (block/edge, warp/head, 2-way interleave) ======
__global__ __launch_bounds__(128) void k_attn() {
    __shared__ int cand[MAXC];
    __shared__ int s_nc;
    __shared__ float sc[NHEAD][MAXC];
    int e = blockIdx.x;
    int tid = threadIdx.x;
    int pk = g_epk[e];
    int qs = pk >> 16, qd = pk & 0xffff;
    if (tid == 0) {
        int n = 0;
        int cs = min(g_cnt[qs], CAP);
        for (int p = 0; p < cs; p++) cand[n++] = g_adj[qs * CAP + p];
        if (qd != qs) {
            int cd = min(g_cnt[qd], CAP);
            for (int p = 0; p < cd; p++) {
                int f = g_adj[qd * CAP + p];
                int fp = g_epk[f];
                if ((fp >> 16) != qs && (fp & 0xffff) != qs) cand[n++] = f;
            }
        }
        s_nc = n;
    }
    __syncthreads();
    int nc = s_nc;
    int h = tid >> 5, lane = tid & 31;
    int off = h * DHEAD + lane;
    float qv = g_q[(size_t)e * DD + off];
    const float scale = 0.17677669529663687f; // 1/sqrt(32)

    // scores: two independent shfl-reduce chains per iteration (halves exposed SHFL latency)
    for (int c = 0; c < nc; c += 2) {
        bool have1 = (c + 1 < nc);
        float t0 = qv * g_k[(size_t)cand[c] * DD + off];
        float t1 = have1 ? qv * g_k[(size_t)cand[c + 1] * DD + off] : 0.f;
#pragma unroll
        for (int o = 16; o; o >>= 1) {
            t0 += __shfl_xor_sync(0xffffffffu, t0, o);
            t1 += __shfl_xor_sync(0xffffffffu, t1, o);
        }
        if (lane == 0) {
            sc[h][c] = t0 * scale;
            if (have1) sc[h][c + 1] = t1 * scale;
        }
    }
    __syncwarp();
    float m = -1e30f;
    for (int c = lane; c < nc; c += 32) m = fmaxf(m, sc[h][c]);
    m = wmax(m);
    float l = 0.f;
    for (int c = lane; c < nc; c += 32) {
        float p = expf(sc[h][c] - m);
        sc[h][c] = p;
        l += p;
    }
    l = wsum(l);
    __syncwarp();

    // weighted V: 2 independent LDG/FMA streams
    float acc0 = 0.f, acc1 = 0.f;
    int c = 0;
    for (; c + 1 < nc; c += 2) {
        acc0 += sc[h][c]     * g_v[(size_t)cand[c] * DD + off];
        acc1 += sc[h][c + 1] * g_v[(size_t)cand[c + 1] * DD + off];
    }
    if (c < nc) acc0 += sc[h][c] * g_v[(size_t)cand[c] * DD + off];
    g_ctx[(size_t)e * DD + off] = (acc0 + acc1) / l;
}

// ============ 4) tail: 32-row tile, 128 thr, 4x8 microtile, K-chunk 32 (R15) ========
// hid = gelu(ctx@Wf + bf + mask*c1); out = hid@W2 + b2. 8 syncs total.
__global__ __launch_bounds__(128) void k_tail(
    const float* __restrict__ W2, const float* __restrict__ b2,
    float* __restrict__ out)
{
    __shared__ __align__(16) float Ast[2][32][36];  // ctx^T [buf][kk(32)][row(32)]
    __shared__ __align__(16) float Bs[2][32][128];  // Wf    [buf][kk(32)][col]
    __shared__ float sm_m[32];

    int tid = threadIdx.x;
    int rb = blockIdx.x * 32;
    if (tid < 32) sm_m[tid] = g_emask[rb + tid] ? 1.f : 0.f;

    int ty = tid >> 4, tx = tid & 15;   // ty 0..7 (4 rows), tx 0..15 (8 cols)
    float acc[4][8];
#pragma unroll
    for (int i = 0; i < 4; i++)
#pragma unroll
        for (int j = 0; j < 8; j++) acc[i][j] = 0.f;

    float aReg[8];
    float4 bReg[8];
    auto loadT = [&](int t) {
        int k0 = t * 32;
#pragma unroll
        for (int l = 0; l < 8; l++) {
            int idx = tid + l * 128;        // 0..1023 over [kk(32) x row(32)]
            int kk = idx & 31, r = idx >> 5;
            aReg[l] = g_ctx[(size_t)(rb + r) * DD + k0 + kk];
        }
        const float4* src = (const float4*)(g_wf + (size_t)k0 * DD);
#pragma unroll
        for (int l = 0; l < 8; l++) bReg[l] = src[tid + l * 128];
    };
    auto storeT = [&](int buf) {
#pragma unroll
        for (int l = 0; l < 8; l++) {
            int idx = tid + l * 128;
            Ast[buf][idx & 31][idx >> 5] = aReg[l];
        }
        float4* dst = (float4*)&Bs[buf][0][0];
#pragma unroll
        for (int l = 0; l < 8; l++) dst[tid + l * 128] = bReg[l];
    };

    loadT(0);
    storeT(0);
    __syncthreads();
    const int T = 4;
    for (int t = 0; t < T; t++) {
        int buf = t & 1;
        if (t + 1 < T) loadT(t + 1);
#pragma unroll
        for (int kk = 0; kk < 32; kk++) {
            float a[4], b[8];
            *(float4*)&a[0] = *(const float4*)&Ast[buf][kk][ty * 4];
            *(float4*)&b[0] = *(const float4*)&Bs[buf][kk][tx * 8];
            *(float4*)&b[4] = *(const float4*)&Bs[buf][kk][tx * 8 + 4];
#pragma unroll
            for (int i = 0; i < 4; i++)
#pragma unroll
                for (int j = 0; j < 8; j++) acc[i][j] += a[i] * b[j];
        }
        __syncthreads();
        if (t + 1 < T) {
            storeT(buf ^ 1);
            __syncthreads();
        }
    }

    // epilogue: + bf + masked c1, gelu (tanh approx = jax.nn.gelu default)
#pragma unroll
    for (int i = 0; i < 4; i++) {
        int r = ty * 4 + i;
        int row = rb + r;
        bool msk = (sm_m[r] != 0.f);
#pragma unroll
        for (int j = 0; j < 8; j++) {
            int col = tx * 8 + j;
            float x = acc[i][j] + g_bf[col];
            if (msk) x += g_c1[(size_t)row * DD + col];
            acc[i][j] = 0.5f * x * (1.f + tanhf(0.7978845608028654f * (x + 0.044715f * x * x * x)));
        }
    }

    // out = hid @ W2 + b2 (register partials + shfl reduce over tx)
    float4 w4[8];
#pragma unroll
    for (int j = 0; j < 8; j++) w4[j] = *(const float4*)&W2[(tx * 8 + j) * 4];

#pragma unroll
    for (int i = 0; i < 4; i++) {
        float p0 = 0.f, p1 = 0.f, p2 = 0.f, p3 = 0.f;
#pragma unroll
        for (int j = 0; j < 8; j++) {
            float h = acc[i][j];
            p0 += h * w4[j].x;
            p1 += h * w4[j].y;
            p2 += h * w4[j].z;
            p3 += h * w4[j].w;
        }
#pragma unroll
        for (int off = 1; off < 16; off <<= 1) {
            p0 += __shfl_xor_sync(0xffffffffu, p0, off);
            p1 += __shfl_xor_sync(0xffffffffu, p1, off);
            p2 += __shfl_xor_sync(0xffffffffu, p2, off);
            p3 += __shfl_xor_sync(0xffffffffu, p3, off);
        }
        if (tx == 0) {
            int row = rb + ty * 4 + i;
            out[row * 4 + 0] = p0 + b2[0];
            out[row * 4 + 1] = p1 + b2[1];
            out[row * 4 + 2] = p2 + b2[2];
            out[row * 4 + 3] = p3 + b2[3];
        }
    }
}

// ---------------- launch ----------------
extern "C" void kernel_launch(void* const* d_in, const int* in_sizes, int n_in,
                              void* d_out, int out_size) {
    const float* nf = (const float*)d_in[0];
    const float* ef = (const float*)d_in[1];
    const int*   ei = (const int*)d_in[2];
    const float* wn = (const float*)d_in[3];
    const float* we = (const float*)d_in[4];
    const float* Wq = (const float*)d_in[5];
    const float* bq = (const float*)d_in[6];
    const float* Wk = (const float*)d_in[7];
    const float* bk = (const float*)d_in[8];
    const float* Wv = (const float*)d_in[9];
    const float* bv = (const float*)d_in[10];
    const float* Wo = (const float*)d_in[11];
    const float* bo = (const float*)d_in[12];
    const float* W1 = (const float*)d_in[13];
    const float* b1 = (const float*)d_in[14];
    const float* W2 = (const float*)d_in[15];
    const float* b2 = (const float*)d_in[16];
    float* out = (float*)d_out;

    k_prep<<<NB, 256>>>(nf, ef, ei, wn, we, Wk, Wv);
    k_kvq<<<NE + DD + 1, 128>>>(ef, Wq, Wk, Wv, W1, bq, bk, bv, Wo, bo, b1);
    k_attn<<<4096, 128>>>();
    k_tail<<<128, 128>>>(W2, b2, out);
}